// round 7
// baseline (speedup 1.0000x reference)
#include <cuda_runtime.h>

// ============================================================================
// MH2SD: attention branch is algebraically dead (softmax over size-1 axis = 1;
// attn rows sum to 1), so out = 1 + gelu(bn(grouped 3x3 conv(x4, local_w))).
//
// R6: 384 threads/CTA (36 warps/SM, occ ~42%), thread tile 1 och x 8 col x
// 2 rows (8 f32x2 accs), 16-way split-K, two-half inner loop to keep live
// registers under the 56-reg cap. Warp = och(8) x (cg,split)(4) -> 8-way
// input broadcast on every LDS.128.
// ============================================================================

#define NPD   24
#define NPIX  576
#define DIMC  128

#define VP_CI        86                    // u64 per ci (3 vrows * 28 used, +2 pad)
#define W_CI         100                   // floats per ci (8 och * 12, +4 pad)
#define W_OFF_BYTES  44032                 // 64 * 86 * 8
#define RED_STRIDE   17                    // u64 stride per output (16 partials + pad)
#define W_REGION     26112                 // max(64*100*4, 192*17*8)
#define SMEM_BYTES   (W_OFF_BYTES + W_REGION)   // 70144

typedef unsigned long long u64;

__device__ __forceinline__ u64 pk(float lo, float hi) {
    u64 r; asm("mov.b64 %0, {%1, %2};" : "=l"(r) : "f"(lo), "f"(hi)); return r;
}
__device__ __forceinline__ void upk(float& lo, float& hi, u64 v) {
    asm("mov.b64 {%0, %1}, %2;" : "=f"(lo), "=f"(hi) : "l"(v));
}
__device__ __forceinline__ void ffma2(u64& d, u64 a, u64 b) {
    asm("fma.rn.f32x2 %0, %1, %2, %0;" : "+l"(d) : "l"(a), "l"(b));
}
__device__ __forceinline__ void fadd2(u64& d, u64 a) {
    asm("add.rn.f32x2 %0, %0, %1;" : "+l"(d) : "l"(a));
}

__global__ void __launch_bounds__(384, 3)
conv_bn_gelu_r6(const float* __restrict__ x,
                const float* __restrict__ lw,
                const float* __restrict__ gamma,
                const float* __restrict__ beta,
                float* __restrict__ out)
{
    extern __shared__ __align__(16) char smem_raw[];
    u64*   vp  = (u64*)smem_raw;                    // [ci][vrow3][k28] vertical pairs
    float* wsm = (float*)(smem_raw + W_OFF_BYTES);  // [ci][och8][12]
    u64*   red = (u64*)(smem_raw + W_OFF_BYTES);    // reused after main loop

    // CTA: 2 batch x 2 group x 8 och-tiles(8 och) x 12 row-tiles(2 rows)
    const int cta = blockIdx.x;
    const int rt  = cta % 12;
    const int ot  = (cta / 12) & 7;
    const int g   = (cta / 96) & 1;
    const int b   = cta / 192;
    const int tid = threadIdx.x;
    const int r0  = rt * 2;

    // ---- halo zeros: k in {0,1} and {26,27} for every (ci, vrow) ----
    if (tid < 192) {
        int ci = tid / 3, vr = tid - ci * 3;     // 192 tasks
        u64* hz = vp + ci * VP_CI + vr * 28;
        ulonglong2 z; z.x = 0ull; z.y = 0ull;
        ((ulonglong2*)hz)[0]        = z;
        ((ulonglong2*)(hz + 26))[0] = z;
    }

    // ---- input staging: coalesced LDG + shfl vertical pairing ----
    // task T = (ci, m, rr), rr fastest: warp covers contiguous 4-row blocks.
    {
        const float4* x4 = (const float4*)x + b * 18432 + g * 9216;
        #pragma unroll
        for (int q = 0; q < 4; q++) {
            int T   = tid + 384 * q;             // 0..1535
            int ci  = T / 24;
            int rem = T - ci * 24;
            int m   = rem >> 2;                  // 0..5 (float4 within row)
            int rr  = rem & 3;                   // 0..3 (row in window)
            int gr  = r0 - 1 + rr;
            float4 F = make_float4(0.f, 0.f, 0.f, 0.f);
            if ((unsigned)gr < 24u) F = x4[ci * 144 + gr * 6 + m];
            float gx = __shfl_down_sync(0xffffffffu, F.x, 1);
            float gy = __shfl_down_sync(0xffffffffu, F.y, 1);
            float gz = __shfl_down_sync(0xffffffffu, F.z, 1);
            float gw = __shfl_down_sync(0xffffffffu, F.w, 1);
            if (rr < 3) {
                u64* dst = vp + ci * VP_CI + rr * 28 + (m * 4 + 2);
                ulonglong2 t0, t1;
                t0.x = pk(F.x, gx); t0.y = pk(F.y, gy);
                t1.x = pk(F.z, gz); t1.y = pk(F.w, gw);
                ((ulonglong2*)dst)[0]       = t0;
                ((ulonglong2*)(dst + 2))[0] = t1;
            }
        }
    }

    // ---- weight staging: linear coalesced copy of contiguous 4608-float blk ----
    {
        const float4* w4 = (const float4*)(lw + (g * 64 + ot * 8) * 576);
        #pragma unroll
        for (int q = 0; q < 3; q++) {
            int i4 = tid + 384 * q;              // 0..1151
            float4 v = w4[i4];
            int i   = i4 * 4;
            int och = i / 576;
            int r   = i - och * 576;
            int ci  = r / 9;
            int tap = r - ci * 9;
            float vals[4] = {v.x, v.y, v.z, v.w};
            float* base = wsm + och * 12;
            #pragma unroll
            for (int e = 0; e < 4; e++) {
                base[ci * W_CI + tap] = vals[e];
                tap++;
                if (tap == 9) { tap = 0; ci++; }
            }
        }
    }

    __syncthreads();

    // ---- roles: och(8) x cg(3 col-groups of 8) x split(16, 4 ci each) ----
    const int och   = tid & 7;
    const int cg    = (tid >> 3) % 3;
    const int split = tid / 24;                  // 0..15

    u64 acc[8];
    #pragma unroll
    for (int j = 0; j < 8; j++) acc[j] = 0ull;

    const u64*   vbase = vp  + (split * 4) * VP_CI + cg * 8;
    const float* wbase = wsm + (split * 4) * W_CI + och * 12;

    #pragma unroll
    for (int i = 0; i < 4; i++) {
        const u64*   vc = vbase + i * VP_CI;
        const float* wc = wbase + i * W_CI;
        #pragma unroll
        for (int di = 0; di < 3; di++) {
            float w0 = wc[di * 3 + 0], w1 = wc[di * 3 + 1], w2 = wc[di * 3 + 2];
            u64 W0 = pk(w0, w0), W1 = pk(w1, w1), W2 = pk(w2, w2);
            const ulonglong2* pv = (const ulonglong2*)(vc + di * 28);

            // half A: j = 0..3 uses P[1..6]
            {
                ulonglong2 q0 = pv[0], q1 = pv[1], q2 = pv[2];
                u64 P6 = *(vc + di * 28 + 6);
                ffma2(acc[0], q0.y, W0); ffma2(acc[0], q1.x, W1); ffma2(acc[0], q1.y, W2);
                ffma2(acc[1], q1.x, W0); ffma2(acc[1], q1.y, W1); ffma2(acc[1], q2.x, W2);
                ffma2(acc[2], q1.y, W0); ffma2(acc[2], q2.x, W1); ffma2(acc[2], q2.y, W2);
                ffma2(acc[3], q2.x, W0); ffma2(acc[3], q2.y, W1); ffma2(acc[3], P6,   W2);
            }
            // half B: j = 4..7 uses P[5..11]
            {
                u64 P5 = *(vc + di * 28 + 5);
                ulonglong2 q3 = pv[3], q4 = pv[4], q5 = pv[5];
                ffma2(acc[4], P5,   W0); ffma2(acc[4], q3.x, W1); ffma2(acc[4], q3.y, W2);
                ffma2(acc[5], q3.x, W0); ffma2(acc[5], q3.y, W1); ffma2(acc[5], q4.x, W2);
                ffma2(acc[6], q3.y, W0); ffma2(acc[6], q4.x, W1); ffma2(acc[6], q4.y, W2);
                ffma2(acc[7], q4.x, W0); ffma2(acc[7], q4.y, W1); ffma2(acc[7], q5.x, W2);
            }
        }
    }

    // ---- split-K reduction (reuse weight region; padded stride 17) ----
    __syncthreads();   // everyone done reading wsm
    {
        const int oidx = och * 24 + cg * 8;      // base output index for this thread
        #pragma unroll
        for (int j = 0; j < 8; j++)
            red[(oidx + j) * RED_STRIDE + split] = acc[j];
    }
    __syncthreads();

    // ---- epilogue: threads 0..191, one (och, col) vertical pair each ----
    if (tid < 192) {
        const int och8 = tid / 24;
        const int col  = tid - och8 * 24;
        const u64* rb  = red + tid * RED_STRIDE;
        u64 tot = rb[0];
        #pragma unroll
        for (int s = 1; s < 16; s++) fadd2(tot, rb[s]);

        const int   ochg = g * 64 + ot * 8 + och8;
        const float sc   = gamma[ochg] * rsqrtf(1.0f + 1e-5f);
        const float bb   = beta[ochg];

        float vt, vb;
        upk(vt, vb, tot);
        float zt = vt * sc + bb;
        float zb = vb * sc + bb;

        const float kI = 0.70710678118654752440f;
        float otv = 1.0f + 0.5f * zt * (1.0f + erff(zt * kI));
        float obv = 1.0f + 0.5f * zb * (1.0f + erff(zb * kI));

        float* opt = out + (b * DIMC + ochg) * NPIX + r0 * NPD + col;
        opt[0]   = otv;
        opt[NPD] = obv;
    }
}

extern "C" void kernel_launch(void* const* d_in, const int* in_sizes, int n_in,
                              void* d_out, int out_size) {
    const float* x     = (const float*)d_in[0];   // (2, 576, 128) flat
    const float* lw    = (const float*)d_in[9];   // local_w (128, 64, 3, 3)
    const float* bnc1g = (const float*)d_in[10];  // bnc1_gamma (128)
    const float* bnc1b = (const float*)d_in[11];  // bnc1_beta (128)
    float* out = (float*)d_out;

    cudaFuncSetAttribute(conv_bn_gelu_r6,
                         cudaFuncAttributeMaxDynamicSharedMemorySize,
                         SMEM_BYTES);
    conv_bn_gelu_r6<<<384, 384, SMEM_BYTES>>>(x, lw, bnc1g, bnc1b, out);
}

// round 8
// speedup vs baseline: 1.1295x; 1.1295x over previous
#include <cuda_runtime.h>

// ============================================================================
// MH2SD: attention branch is algebraically dead (softmax over size-1 axis = 1;
// attn rows sum to 1), so out = 1 + gelu(bn(grouped 3x3 conv(x4, local_w))).
//
// R7: 256 threads/CTA @ 3 CTAs/SM -> 24 warps/SM with an 84-register budget
// so ptxas can pipeline LDS across unrolled blocks (R6's 56-reg cap blocked
// this). Roles och(8) x cg(4 x 6 cols) x split(8 x 8 ci); thread tile
// 1 och x 6 col x 2 rows = 6 f32x2 accs.
// ============================================================================

#define NPD   24
#define NPIX  576
#define DIMC  128

#define VP_CI        86                    // u64 per ci (3 vrows * 28 used, +2 pad)
#define W_CI         100                   // floats per ci (8 och * 12, +4 pad)
#define W_OFF_BYTES  44032                 // 64 * 86 * 8
#define RED_STRIDE   9                     // u64 stride per output (8 partials + pad)
#define W_REGION     25600                 // max(64*100*4, 192*9*8=13824)
#define SMEM_BYTES   (W_OFF_BYTES + W_REGION)   // 69632

typedef unsigned long long u64;

__device__ __forceinline__ u64 pk(float lo, float hi) {
    u64 r; asm("mov.b64 %0, {%1, %2};" : "=l"(r) : "f"(lo), "f"(hi)); return r;
}
__device__ __forceinline__ void upk(float& lo, float& hi, u64 v) {
    asm("mov.b64 {%0, %1}, %2;" : "=f"(lo), "=f"(hi) : "l"(v));
}
__device__ __forceinline__ void ffma2(u64& d, u64 a, u64 b) {
    asm("fma.rn.f32x2 %0, %1, %2, %0;" : "+l"(d) : "l"(a), "l"(b));
}
__device__ __forceinline__ void fadd2(u64& d, u64 a) {
    asm("add.rn.f32x2 %0, %0, %1;" : "+l"(d) : "l"(a));
}

__global__ void __launch_bounds__(256, 3)
conv_bn_gelu_r7(const float* __restrict__ x,
                const float* __restrict__ lw,
                const float* __restrict__ gamma,
                const float* __restrict__ beta,
                float* __restrict__ out)
{
    extern __shared__ __align__(16) char smem_raw[];
    u64*   vp  = (u64*)smem_raw;                    // [ci][vrow3][k28] vertical pairs
    float* wsm = (float*)(smem_raw + W_OFF_BYTES);  // [ci][och8][12]
    u64*   red = (u64*)(smem_raw + W_OFF_BYTES);    // reused after main loop

    // CTA: 2 batch x 2 group x 8 och-tiles(8 och) x 12 row-tiles(2 rows)
    const int cta = blockIdx.x;
    const int rt  = cta % 12;
    const int ot  = (cta / 12) & 7;
    const int g   = (cta / 96) & 1;
    const int b   = cta / 192;
    const int tid = threadIdx.x;
    const int r0  = rt * 2;

    // ---- halo zeros: k in {0,1} and {26,27} for every (ci, vrow) ----
    if (tid < 192) {
        int ci = tid / 3, vr = tid - ci * 3;     // 192 tasks
        u64* hz = vp + ci * VP_CI + vr * 28;
        ulonglong2 z; z.x = 0ull; z.y = 0ull;
        ((ulonglong2*)hz)[0]        = z;
        ((ulonglong2*)(hz + 26))[0] = z;
    }

    // ---- input staging: coalesced LDG + shfl vertical pairing ----
    // task T = (ci, m, rr), rr fastest: warp covers contiguous 4-row blocks.
    // lane parity: 256 ≡ 0 (mod 4) so rr == T&3 == lane&3 pattern holds and
    // the rr<3 partner (T+1) is always lane+1 within the same warp.
    {
        const float4* x4 = (const float4*)x + b * 18432 + g * 9216;
        #pragma unroll
        for (int q = 0; q < 6; q++) {
            int T   = tid + 256 * q;             // 0..1535
            int ci  = T / 24;
            int rem = T - ci * 24;
            int m   = rem >> 2;                  // 0..5 (float4 within row)
            int rr  = rem & 3;                   // 0..3 (row in window)
            int gr  = r0 - 1 + rr;
            float4 F = make_float4(0.f, 0.f, 0.f, 0.f);
            if ((unsigned)gr < 24u) F = x4[ci * 144 + gr * 6 + m];
            float gx = __shfl_down_sync(0xffffffffu, F.x, 1);
            float gy = __shfl_down_sync(0xffffffffu, F.y, 1);
            float gz = __shfl_down_sync(0xffffffffu, F.z, 1);
            float gw = __shfl_down_sync(0xffffffffu, F.w, 1);
            if (rr < 3) {
                u64* dst = vp + ci * VP_CI + rr * 28 + (m * 4 + 2);
                ulonglong2 t0, t1;
                t0.x = pk(F.x, gx); t0.y = pk(F.y, gy);
                t1.x = pk(F.z, gz); t1.y = pk(F.w, gw);
                ((ulonglong2*)dst)[0]       = t0;
                ((ulonglong2*)(dst + 2))[0] = t1;
            }
        }
    }

    // ---- weight staging: linear coalesced copy of contiguous 4608-float blk ----
    {
        const float4* w4 = (const float4*)(lw + (g * 64 + ot * 8) * 576);
        #pragma unroll
        for (int q = 0; q < 5; q++) {
            int i4 = tid + 256 * q;              // 0..1151
            if (i4 < 1152) {
                float4 v = w4[i4];
                int i   = i4 * 4;
                int och = i / 576;
                int r   = i - och * 576;
                int ci  = r / 9;
                int tap = r - ci * 9;
                float vals[4] = {v.x, v.y, v.z, v.w};
                float* base = wsm + och * 12;
                #pragma unroll
                for (int e = 0; e < 4; e++) {
                    base[ci * W_CI + tap] = vals[e];
                    tap++;
                    if (tap == 9) { tap = 0; ci++; }
                }
            }
        }
    }

    __syncthreads();

    // ---- roles: och(8) x cg(4 col-groups of 6) x split(8, 8 ci each) ----
    const int och   = tid & 7;
    const int cg    = (tid >> 3) & 3;
    const int split = tid >> 5;                  // 0..7 (== warp id)

    u64 acc[6];
    #pragma unroll
    for (int j = 0; j < 6; j++) acc[j] = 0ull;

    const u64*   vbase = vp  + (split * 8) * VP_CI + cg * 6;
    const float* wbase = wsm + (split * 8) * W_CI + och * 12;

    #pragma unroll
    for (int i = 0; i < 8; i++) {
        const u64*   vc = vbase + i * VP_CI;
        const float* wc = wbase + i * W_CI;
        #pragma unroll
        for (int di = 0; di < 3; di++) {
            float w0 = wc[di * 3 + 0], w1 = wc[di * 3 + 1], w2 = wc[di * 3 + 2];
            u64 W0 = pk(w0, w0), W1 = pk(w1, w1), W2 = pk(w2, w2);
            const ulonglong2* pv = (const ulonglong2*)(vc + di * 28);
            ulonglong2 q0 = pv[0], q1 = pv[1], q2 = pv[2], q3 = pv[3];
            u64 P8 = *(vc + di * 28 + 8);
            // acc[j] (local col j) taps local k = j+1, j+2, j+3
            ffma2(acc[0], q0.y, W0); ffma2(acc[0], q1.x, W1); ffma2(acc[0], q1.y, W2);
            ffma2(acc[1], q1.x, W0); ffma2(acc[1], q1.y, W1); ffma2(acc[1], q2.x, W2);
            ffma2(acc[2], q1.y, W0); ffma2(acc[2], q2.x, W1); ffma2(acc[2], q2.y, W2);
            ffma2(acc[3], q2.x, W0); ffma2(acc[3], q2.y, W1); ffma2(acc[3], q3.x, W2);
            ffma2(acc[4], q2.y, W0); ffma2(acc[4], q3.x, W1); ffma2(acc[4], q3.y, W2);
            ffma2(acc[5], q3.x, W0); ffma2(acc[5], q3.y, W1); ffma2(acc[5], P8,   W2);
        }
    }

    // ---- split-K reduction (reuse weight region; padded stride 9) ----
    __syncthreads();   // everyone done reading wsm
    {
        const int oidx = och * 24 + cg * 6;      // base output index for this thread
        #pragma unroll
        for (int j = 0; j < 6; j++)
            red[(oidx + j) * RED_STRIDE + split] = acc[j];
    }
    __syncthreads();

    // ---- epilogue: threads 0..191, one (och, col) vertical pair each ----
    if (tid < 192) {
        const int och8 = tid / 24;
        const int col  = tid - och8 * 24;
        const u64* rb  = red + tid * RED_STRIDE;
        u64 tot = rb[0];
        #pragma unroll
        for (int s = 1; s < 8; s++) fadd2(tot, rb[s]);

        const int   ochg = g * 64 + ot * 8 + och8;
        const float sc   = gamma[ochg] * rsqrtf(1.0f + 1e-5f);
        const float bb   = beta[ochg];

        float vt, vb;
        upk(vt, vb, tot);
        float zt = vt * sc + bb;
        float zb = vb * sc + bb;

        const float kI = 0.70710678118654752440f;
        float otv = 1.0f + 0.5f * zt * (1.0f + erff(zt * kI));
        float obv = 1.0f + 0.5f * zb * (1.0f + erff(zb * kI));

        float* opt = out + (b * DIMC + ochg) * NPIX + r0 * NPD + col;
        opt[0]   = otv;
        opt[NPD] = obv;
    }
}

extern "C" void kernel_launch(void* const* d_in, const int* in_sizes, int n_in,
                              void* d_out, int out_size) {
    const float* x     = (const float*)d_in[0];   // (2, 576, 128) flat
    const float* lw    = (const float*)d_in[9];   // local_w (128, 64, 3, 3)
    const float* bnc1g = (const float*)d_in[10];  // bnc1_gamma (128)
    const float* bnc1b = (const float*)d_in[11];  // bnc1_beta (128)
    float* out = (float*)d_out;

    cudaFuncSetAttribute(conv_bn_gelu_r7,
                         cudaFuncAttributeMaxDynamicSharedMemorySize,
                         SMEM_BYTES);
    conv_bn_gelu_r7<<<384, 256, SMEM_BYTES>>>(x, lw, bnc1g, bnc1b, out);
}